// round 12
// baseline (speedup 1.0000x reference)
#include <cuda_runtime.h>

#define NTP 512   // pass threads

typedef unsigned long long ull;

// 8 MB state (packed complex), tables, splatted unitaries — __device__ globals.
__device__ ull g_psi[16 * 65536];
// Splatted coeffs: per gate 8 float2: [2k]=(re,re), [2k+1]=(-im,im) for coeff k.
__device__ float2 g_U2[480];
// Factored layer-0 ring-phase tables: phase(i) = lo[i&0x1FF] * hi[(i>>8)&0xFF | (i&1)<<8]
__device__ float2 g_f0lo[512], g_f0hi[512];   // depth 0
__device__ float2 g_f1lo[512], g_f1hi[512];   // depth 1
__device__ float2 g_t1[512];       // layer1 ring phases (2 depths x 256)
__device__ float2 g_t2[32];        // layer2 (2 x 16)
__device__ float2 g_t3[8];         // layer3 (2 x 4)

__device__ __forceinline__ float2 cmul(float2 a, float2 b) {
    return make_float2(fmaf(a.x, b.x, -a.y * b.y), fmaf(a.x, b.y, a.y * b.x));
}
__device__ __forceinline__ float2 cadd(float2 a, float2 b) {
    return make_float2(a.x + b.x, a.y + b.y);
}
__device__ __forceinline__ void mm2(const float2* A, const float2* B, float2* C) {
    C[0] = cadd(cmul(A[0], B[0]), cmul(A[1], B[2]));
    C[1] = cadd(cmul(A[0], B[1]), cmul(A[1], B[3]));
    C[2] = cadd(cmul(A[2], B[0]), cmul(A[3], B[2]));
    C[3] = cadd(cmul(A[2], B[1]), cmul(A[3], B[3]));
}

// ---- packed f32x2 helpers (sm_100+ PTX) ----
__device__ __forceinline__ ull qfma(ull a, ull b, ull c) {
    ull d; asm("fma.rn.f32x2 %0, %1, %2, %3;" : "=l"(d) : "l"(a), "l"(b), "l"(c)); return d;
}
__device__ __forceinline__ ull qmul(ull a, ull b) {
    ull d; asm("mul.rn.f32x2 %0, %1, %2;" : "=l"(d) : "l"(a), "l"(b)); return d;
}
__device__ __forceinline__ ull csw(ull v) {   // (x,y) -> (y,x)
    ull r;
    asm("{\n\t.reg .b32 x, y;\n\tmov.b64 {x, y}, %1;\n\tmov.b64 %0, {y, x};\n\t}"
        : "=l"(r) : "l"(v));
    return r;
}
__device__ __forceinline__ ull pkf2(float2 v) {
    ull r; asm("mov.b64 %0, {%1, %2};" : "=l"(r) : "f"(v.x), "f"(v.y)); return r;
}
__device__ __forceinline__ float2 upkf2(ull v) {
    float2 r; asm("mov.b64 {%0, %1}, %2;" : "=f"(r.x), "=f"(r.y) : "l"(v)); return r;
}

// Bank-conflict-killing swizzle (involution): XOR low nibble with bits 4-7.
__device__ __forceinline__ int SWZ(int i) { return i ^ ((i >> 4) & 15); }
// Insert a zero bit at position B.
__device__ __forceinline__ int insb(int x, int B) {
    return ((x >> B) << (B + 1)) | (x & ((1 << B) - 1));
}

// Layer-0 factored ring phase lookup (full 16-bit amp index, batch-free).
__device__ __forceinline__ float2 ring0_d0(int i) {
    return cmul(g_f0lo[i & 0x1FF], g_f0hi[((i >> 8) & 0xFF) | ((i & 1) << 8)]);
}
__device__ __forceinline__ float2 ring0_d1(int i) {
    return cmul(g_f1lo[i & 0x1FF], g_f1hi[((i >> 8) & 0xFF) | ((i & 1) << 8)]);
}

// ---------------------------------------------------------------------------
// Prep (tiny): factored ring tables, small ring tables, 60 splatted unitaries.
// Ring term j couples amp bits (15-j) and (15-(j+1 mod 16)).
// ---------------------------------------------------------------------------
__global__ __launch_bounds__(512) void prep_kernel(
    const float* __restrict__ p0, const float* __restrict__ p1,
    const float* __restrict__ p2, const float* __restrict__ p3,
    float* __restrict__ out)
{
    int T = blockIdx.x * 512 + threadIdx.x;

    if (T < 512) {                      // lo tables (amp bits 8..0)
        float ph0 = 0.f, ph1 = 0.f;
        #pragma unroll
        for (int j = 7; j < 15; j++) {
            int x = ((T >> (15 - j)) ^ (T >> (14 - j))) & 1;
            float sg = x ? 0.5f : -0.5f;
            ph0 += sg * p0[4 * j + 3];
            ph1 += sg * p0[4 * j + 67];
        }
        g_f0lo[T] = make_float2(cosf(ph0), sinf(ph0));
        g_f1lo[T] = make_float2(cosf(ph1), sinf(ph1));
    } else if (T < 1024) {              // hi tables
        int ih = T - 512;
        float ph0 = 0.f, ph1 = 0.f;
        #pragma unroll
        for (int j = 0; j < 7; j++) {
            int x = ((ih >> (7 - j)) ^ (ih >> (6 - j))) & 1;
            float sg = x ? 0.5f : -0.5f;
            ph0 += sg * p0[4 * j + 3];
            ph1 += sg * p0[4 * j + 67];
        }
        {   // term j=15: amp bits 0 (ih bit 8) and 15 (ih bit 7)
            int x = ((ih >> 8) ^ (ih >> 7)) & 1;
            float sg = x ? 0.5f : -0.5f;
            ph0 += sg * p0[63];
            ph1 += sg * p0[127];
        }
        g_f0hi[ih] = make_float2(cosf(ph0), sinf(ph0));
        g_f1hi[ih] = make_float2(cosf(ph1), sinf(ph1));
    } else if (T < 1536) {              // layer1 ring (8 wires), 2 depths x 256
        int tt = T - 1024;
        int d = tt >> 8, idx = tt & 255;
        float ph = 0.f;
        #pragma unroll
        for (int j = 0; j < 8; j++) {
            int jn = (j + 1) & 7;
            int x = ((idx >> (7 - j)) ^ (idx >> (7 - jn))) & 1;
            ph += (x ? 0.5f : -0.5f) * p1[4 * j + 3 + 32 * d];
        }
        g_t1[tt] = make_float2(cosf(ph), sinf(ph));
    } else if (T < 1568) {              // layer2 ring (4 wires)
        int tt = T - 1536;
        int d = tt >> 4, idx = tt & 15;
        float ph = 0.f;
        #pragma unroll
        for (int j = 0; j < 4; j++) {
            int jn = (j + 1) & 3;
            int x = ((idx >> (3 - j)) ^ (idx >> (3 - jn))) & 1;
            ph += (x ? 0.5f : -0.5f) * p2[4 * j + 3 + 16 * d];
        }
        g_t2[tt] = make_float2(cosf(ph), sinf(ph));
    } else if (T < 1576) {              // layer3 (2 wires)
        int tt = T - 1568;
        int d = tt >> 2, idx = tt & 3;
        int x = ((idx >> 1) ^ idx) & 1;
        float sg = x ? 0.5f : -0.5f;
        float ph = sg * (p3[3 + 8 * d] + p3[7 + 8 * d]);
        g_t3[tt] = make_float2(cosf(ph), sinf(ph));
    } else if (T >= 1600 && T < 1660) { // compose + splat 60 unitaries
        int t = T - 1600;
        const float* pp; int base;
        if (t < 32)      { pp = p0; int d = t >> 4;        int s = t & 15;       base = 4 * s + 64 * d; }
        else if (t < 48) { pp = p1; int d = (t - 32) >> 3; int s = (t - 32) & 7; base = 4 * s + 32 * d; }
        else if (t < 56) { pp = p2; int d = (t - 48) >> 2; int s = (t - 48) & 3; base = 4 * s + 16 * d; }
        else             { pp = p3; int d = (t - 56) >> 1; int s = (t - 56) & 1; base = 4 * s + 8 * d; }
        float a = pp[base] * 0.5f, b = pp[base + 1] * 0.5f, c = pp[base + 2] * 0.5f;
        float ca = cosf(a), sa = sinf(a);
        float cb = cosf(b), sb = sinf(b);
        float cc = cosf(c), sc = sinf(c);
        float2 RXa[4] = { {ca,0.f}, {0.f,-sa}, {0.f,-sa}, {ca,0.f} };
        float2 RZb[4] = { {cb,-sb}, {0.f,0.f}, {0.f,0.f}, {cb,sb} };
        float2 RXc[4] = { {cc,0.f}, {0.f,-sc}, {0.f,-sc}, {cc,0.f} };
        float2 M[4], U[4];
        mm2(RZb, RXa, M);
        mm2(RXc, M, U);
        #pragma unroll
        for (int k = 0; k < 4; k++) {
            g_U2[t * 8 + 2 * k]     = make_float2(U[k].x, U[k].x);
            g_U2[t * 8 + 2 * k + 1] = make_float2(-U[k].y, U[k].y);
        }
    } else if (T >= 1664 && T < 1680) {
        out[T - 1664] = 0.f;
    }
}

// ---------------------------------------------------------------------------
// 2-gate cell sweep (f32x2 engine): gate uh on bit BH, ul on BL (BH > BL).
// 1024 cells of 4 packed amps, 512 threads x 2 iterations.
// Complex mult: U*a = (Ure,Ure).a + (-Uim,Uim).swap(a), all lane-wise f32x2.
// Caller appends __syncthreads() when needed.
// ---------------------------------------------------------------------------
template<int BH, int BL, class LDF, class STF>
__device__ __forceinline__ void cell2(int uh, int ul, LDF ld, STF st) {
    const ull* CL = reinterpret_cast<const ull*>(g_U2) + ul * 8;
    const ull* CH = reinterpret_cast<const ull*>(g_U2) + uh * 8;
    const ull L0r = CL[0], L0i = CL[1], L1r = CL[2], L1i = CL[3];
    const ull L2r = CL[4], L2i = CL[5], L3r = CL[6], L3i = CL[7];
    const ull H0r = CH[0], H0i = CH[1], H1r = CH[2], H1i = CH[3];
    const ull H2r = CH[4], H2i = CH[5], H3r = CH[6], H3i = CH[7];
    #pragma unroll
    for (int it = 0; it < 2; it++) {
        int c = threadIdx.x + it * NTP;
        int base = insb(insb(c, BL), BH);
        int i01 = base | (1 << BL);
        int i10 = base | (1 << BH);
        int i11 = i10 | (1 << BL);
        ull a00 = ld(base), a01 = ld(i01), a10 = ld(i10), a11 = ld(i11);
        ull s00 = csw(a00), s01 = csw(a01), s10 = csw(a10), s11 = csw(a11);
        // gate on BL: pairs (a00,a01), (a10,a11)
        ull b00 = qfma(L0r, a00, qfma(L0i, s00, qfma(L1r, a01, qmul(L1i, s01))));
        ull b01 = qfma(L2r, a00, qfma(L2i, s00, qfma(L3r, a01, qmul(L3i, s01))));
        ull b10 = qfma(L0r, a10, qfma(L0i, s10, qfma(L1r, a11, qmul(L1i, s11))));
        ull b11 = qfma(L2r, a10, qfma(L2i, s10, qfma(L3r, a11, qmul(L3i, s11))));
        ull t00 = csw(b00), t01 = csw(b01), t10 = csw(b10), t11 = csw(b11);
        // gate on BH: pairs (b00,b10), (b01,b11)
        ull r00 = qfma(H0r, b00, qfma(H0i, t00, qfma(H1r, b10, qmul(H1i, t10))));
        ull r10 = qfma(H2r, b00, qfma(H2i, t00, qfma(H3r, b10, qmul(H3i, t10))));
        ull r01 = qfma(H0r, b01, qfma(H0i, t01, qfma(H1r, b11, qmul(H1i, t11))));
        ull r11 = qfma(H2r, b01, qfma(H2i, t01, qfma(H3r, b11, qmul(H3i, t11))));
        st(base, r00); st(i01, r01); st(i10, r10); st(i11, r11);
    }
}

// ---------------------------------------------------------------------------
// Fused diagonal + CNOT-layer permutation (XOR involution). new[l]=old[p]*ph(p).
// ---------------------------------------------------------------------------
template<class FXF, class PHF>
__device__ __forceinline__ void perm_ph(ull* s, FXF fx, PHF ph) {
    #pragma unroll
    for (int i = 0; i < 8; i++) {
        int l = threadIdx.x + i * NTP;
        int f = fx(l);
        int p = l ^ f;
        if (f == 0) {
            s[SWZ(l)] = pkf2(cmul(upkf2(s[SWZ(l)]), ph(l)));
        } else if (l < p) {
            float2 a = upkf2(s[SWZ(l)]), b = upkf2(s[SWZ(p)]);
            s[SWZ(l)] = pkf2(cmul(b, ph(p)));
            s[SWZ(p)] = pkf2(cmul(a, ph(l)));
        }
    }
    __syncthreads();
}

// ---------------------------------------------------------------------------
// Pass 1: local = amp bits 0..11 (wires 4..15). Layer0 d0 on wires 4..15.
// ---------------------------------------------------------------------------
__global__ __launch_bounds__(NTP, 2) void pass1_kernel(
    const float* __restrict__ xre, const float* __restrict__ xim)
{
    __shared__ ull s[4096];
    int b = blockIdx.x >> 4, tile = blockIdx.x & 15;
    int base = (b << 16) | (tile << 12);
    auto SLD = [&](int l) { return s[SWZ(l)]; };
    auto SST = [&](int l, ull v) { s[SWZ(l)] = v; };
    cell2<11, 0>(4, 15,
        [&](int l) { return pkf2(make_float2(xre[base + l], xim[base + l])); }, SST);
    __syncthreads();
    cell2<10, 1>(5, 14, SLD, SST); __syncthreads();
    cell2<9, 2>(6, 13, SLD, SST);  __syncthreads();
    cell2<8, 3>(7, 12, SLD, SST);  __syncthreads();
    cell2<7, 4>(8, 11, SLD, SST);  __syncthreads();
    cell2<6, 5>(9, 10, SLD, [&](int l, ull v) { g_psi[base + l] = v; });
}

// ---------------------------------------------------------------------------
// Pass 2: local amp bits {0-4,7,9,11,12-15}. d0 on wires 0-3; ring D0; d1 on
// 12 local wires. Global amp bits {5,6,8,10}.
// ---------------------------------------------------------------------------
__device__ __forceinline__ int expand2x(int l) {
    return (l & 0x1F) | ((l & 0x20) << 2) | ((l & 0x40) << 3) | ((l & 0xF80) << 4);
}
__global__ __launch_bounds__(NTP, 2) void pass2_kernel() {
    __shared__ ull s[4096];
    int b = blockIdx.x >> 4, tile = blockIdx.x & 15;
    unsigned tor = ((tile & 3) << 5) | ((tile & 4) << 6) | ((tile & 8) << 7);
    unsigned gb = (unsigned)b << 16;
    auto SLD = [&](int l) { return s[SWZ(l)]; };
    auto SST = [&](int l, ull v) { s[SWZ(l)] = v; };
    // layer0 d0 on wires 0..3 (locals 11,10,9,8) — first sweep fused with load
    cell2<11, 8>(0, 3, [&](int l) { return g_psi[gb | tor | expand2x(l)]; }, SST);
    __syncthreads();
    cell2<10, 9>(1, 2, SLD, SST); __syncthreads();
    // layer0 d1, ring diag D0 folded into the first sweep's load
    cell2<11, 0>(16, 31,
        [&](int l) { return pkf2(cmul(upkf2(s[SWZ(l)]), ring0_d0(tor | expand2x(l)))); }, SST);
    __syncthreads();
    cell2<10, 1>(17, 30, SLD, SST); __syncthreads();
    cell2<9, 2>(18, 29, SLD, SST);  __syncthreads();
    cell2<8, 3>(19, 28, SLD, SST);  __syncthreads();
    cell2<7, 4>(20, 27, SLD, SST);  __syncthreads();
    cell2<6, 5>(22, 24, SLD,
        [&](int l, ull v) { g_psi[gb | tor | expand2x(l)] = v; });
}

// ---------------------------------------------------------------------------
// Pass 3: local amp bits {0-6,8,10,12,14,15}. Global amp bits {7,9,11,13}.
// Local map: l11=w0 l10=w1 l9=w3 l8=w5 l7=w7 l6=w9 l5=w10 l4..l0=w11..w15.
// ---------------------------------------------------------------------------
__device__ __forceinline__ int expand3x(int l) {
    return (l & 0x7F) | ((l & 0x80) << 1) | ((l & 0x100) << 2) |
           ((l & 0x200) << 3) | ((l & 0xC00) << 4);
}
__global__ __launch_bounds__(NTP, 2) void pass3_kernel() {
    __shared__ ull s[4096];
    int b = blockIdx.x >> 4, tile = blockIdx.x & 15;
    unsigned tor = ((tile & 1) << 7) | ((tile & 2) << 8) | ((tile & 4) << 9) | ((tile & 8) << 10);
    unsigned gb = (unsigned)b << 16;
    auto SLD = [&](int l) { return s[SWZ(l)]; };
    auto SST = [&](int l, ull v) { s[SWZ(l)] = v; };
    // layer0 d1 leftovers: w5->l8(U21), w7->l7(U23), w9->l6(U25), w10->l5(U26)
    cell2<8, 5>(21, 26, [&](int l) { return g_psi[gb | tor | expand3x(l)]; }, SST);
    __syncthreads();
    cell2<7, 6>(23, 25, SLD, SST); __syncthreads();
    // ring D1 + all 8 pool CNOTs fused (targets l10,l9,l8,l7,l6,l4,l2,l0).
    {
        int fc = (((tile >> 3) & 1) << 9) | (((tile >> 2) & 1) << 8) |
                 (((tile >> 1) & 1) << 7) | ((tile & 1) << 6);
        perm_ph(s,
            [&](int l) {
                return ((((l >> 11) & 1) << 10) | (((l >> 5) & 1) << 4) |
                        (((l >> 3) & 1) << 2) | ((l >> 1) & 1)) | fc;
            },
            [&](int l) { return ring0_d1(tor | expand3x(l)); });
    }
    // layer1 d0 on wires 0,10,12,14 -> locals 11(U32),5(U37),3(U38),1(U39)
    cell2<11, 1>(32, 39, SLD, SST); __syncthreads();
    cell2<5, 3>(37, 38, SLD,
        [&](int l, ull v) { g_psi[gb | tor | expand3x(l)] = v; });
}

// ---------------------------------------------------------------------------
// Pass 4: local amp bits {0-7,9,11,13,15}. Global amp bits {8,10,12,14}.
// Local map: l11=w0 l10=w2 l9=w4 l8=w6 l7=w8 l5=w10 l3=w12 l1=w14.
// Final diagonal (t3 d1) and final pool CNOT (ctrl=bit11, tgt=bit7) cannot
// change <Z(bit11)> — dropped. Measurement fused into the last unitary sweep.
// ---------------------------------------------------------------------------
__device__ __forceinline__ int expand4x(int l) {
    return (l & 0xFF) | ((l & 0x100) << 1) | ((l & 0x200) << 2) |
           ((l & 0x400) << 3) | ((l & 0x800) << 4);
}
__device__ __forceinline__ int p4_idx8(int l) {
    return ((l >> 4) & 0xF8) | ((l >> 3) & 4) | ((l >> 2) & 2) | ((l >> 1) & 1);
}
__device__ __forceinline__ int p4_idx4(int l) {
    return ((l >> 8) & 8) | ((l >> 7) & 4) | ((l >> 6) & 2) | ((l >> 3) & 1);
}
__device__ __forceinline__ int p4_idx2(int l) {
    return ((l >> 10) & 2) | ((l >> 7) & 1);
}
__global__ __launch_bounds__(NTP, 2) void pass4_kernel(float* __restrict__ out) {
    __shared__ ull s[4096];
    __shared__ float ws[16];
    int tid = threadIdx.x;
    int b = blockIdx.x >> 4, tile = blockIdx.x & 15;
    unsigned tor = ((tile & 1) << 8) | ((tile & 2) << 9) | ((tile & 4) << 10) | ((tile & 8) << 11);
    unsigned gb = (unsigned)b << 16;
    auto SLD = [&](int l) { return s[SWZ(l)]; };
    auto SST = [&](int l, ull v) { s[SWZ(l)] = v; };

    // layer1 d0 leftovers: w2->l10(U33), w4->l9(U34), w6->l8(U35), w8->l7(U36)
    cell2<10, 7>(33, 36, [&](int l) { return g_psi[gb | tor | expand4x(l)]; }, SST);
    __syncthreads();
    cell2<9, 8>(34, 35, SLD, SST); __syncthreads();
    // layer1 d1 (8 gates) with ring d0 folded into the first sweep
    cell2<11, 1>(40, 47,
        [&](int l) { return pkf2(cmul(upkf2(s[SWZ(l)]), g_t1[p4_idx8(l)])); }, SST);
    __syncthreads();
    cell2<10, 3>(41, 46, SLD, SST); __syncthreads();
    cell2<9, 5>(42, 45, SLD, SST);  __syncthreads();
    cell2<8, 7>(43, 44, SLD, SST);  __syncthreads();
    // ring d1 + layer1 pool (l10<-l11, l8<-l9, l5<-l7, l1<-l3)
    perm_ph(s,
        [&](int l) {
            return (((l >> 11) & 1) << 10) | (((l >> 9) & 1) << 8) |
                   (((l >> 7) & 1) << 5) | (((l >> 3) & 1) << 1);
        },
        [&](int l) { return g_t1[256 + p4_idx8(l)]; });

    // layer2 d0: w0->l11(U48), w4->l9(U49), w8->l7(U50), w12->l3(U51)
    cell2<11, 3>(48, 51, SLD, SST); __syncthreads();
    cell2<9, 7>(49, 50, SLD, SST);  __syncthreads();
    // layer2 d1 with ring d0 folded
    cell2<11, 3>(52, 55,
        [&](int l) { return pkf2(cmul(upkf2(s[SWZ(l)]), g_t2[p4_idx4(l)])); }, SST);
    __syncthreads();
    cell2<9, 7>(53, 54, SLD, SST); __syncthreads();
    // ring d1 + layer2 pool (l9<-l11, l3<-l7)
    perm_ph(s,
        [&](int l) {
            return (((l >> 11) & 1) << 9) | (((l >> 7) & 1) << 3);
        },
        [&](int l) { return g_t2[16 + p4_idx4(l)]; });

    // layer3 d0: w0->l11(U56), w8->l7(U57)
    cell2<11, 7>(56, 57, SLD, SST); __syncthreads();
    // layer3 d1 sweep (U58 on l11, U59 on l7) with t3-d0 phase folded,
    // fused with Z-measurement on l11. t3-d1 + pool3 provably no-op for <Z>.
    float acc = 0.f;
    cell2<11, 7>(58, 59,
        [&](int l) { return pkf2(cmul(upkf2(s[SWZ(l)]), g_t3[p4_idx2(l)])); },
        [&](int l, ull v) {
            float2 f = upkf2(v);
            float p = fmaf(f.x, f.x, f.y * f.y);
            acc += ((l >> 11) & 1) ? -p : p;
        });

    #pragma unroll
    for (int o = 16; o > 0; o >>= 1) acc += __shfl_xor_sync(0xFFFFFFFFu, acc, o);
    if ((tid & 31) == 0) ws[tid >> 5] = acc;
    __syncthreads();
    if (tid == 0) {
        float t = 0.f;
        #pragma unroll
        for (int k = 0; k < 16; k++) t += ws[k];
        atomicAdd(&out[b], t);
    }
}

// ---------------------------------------------------------------------------
extern "C" void kernel_launch(void* const* d_in, const int* in_sizes, int n_in,
                              void* d_out, int out_size) {
    const float* xre = (const float*)d_in[0];
    const float* xim = (const float*)d_in[1];
    const float* p0  = (const float*)d_in[2];
    const float* p1  = (const float*)d_in[3];
    const float* p2  = (const float*)d_in[4];
    const float* p3  = (const float*)d_in[5];
    float* out = (float*)d_out;

    prep_kernel<<<8, 512>>>(p0, p1, p2, p3, out);
    pass1_kernel<<<256, NTP>>>(xre, xim);
    pass2_kernel<<<256, NTP>>>();
    pass3_kernel<<<256, NTP>>>();
    pass4_kernel<<<256, NTP>>>(out);
}

// round 13
// speedup vs baseline: 1.0830x; 1.0830x over previous
#include <cuda_runtime.h>

#define NTP 512   // pass threads

// 8 MB state, tables, composed unitaries — all __device__ globals (no allocs).
__device__ float2 g_psi[16 * 65536];
__device__ float2 g_U[240];        // 60 composed 2x2 unitaries
// Factored layer-0 ring-phase tables: phase(i) = lo[i&0x1FF] * hi[(i>>8)&0xFF | (i&1)<<8]
__device__ float2 g_f0lo[512], g_f0hi[512];   // depth 0
__device__ float2 g_f1lo[512], g_f1hi[512];   // depth 1
__device__ float2 g_t1[512];       // layer1 ring phases (2 depths x 256)
__device__ float2 g_t2[32];        // layer2 (2 x 16)
__device__ float2 g_t3[8];         // layer3 (2 x 4)

__device__ __forceinline__ float2 cmul(float2 a, float2 b) {
    return make_float2(fmaf(a.x, b.x, -a.y * b.y), fmaf(a.x, b.y, a.y * b.x));
}
__device__ __forceinline__ float2 cadd(float2 a, float2 b) {
    return make_float2(a.x + b.x, a.y + b.y);
}
__device__ __forceinline__ void mm2(const float2* A, const float2* B, float2* C) {
    C[0] = cadd(cmul(A[0], B[0]), cmul(A[1], B[2]));
    C[1] = cadd(cmul(A[0], B[1]), cmul(A[1], B[3]));
    C[2] = cadd(cmul(A[2], B[0]), cmul(A[3], B[2]));
    C[3] = cadd(cmul(A[2], B[1]), cmul(A[3], B[3]));
}

// Bank-conflict-killing swizzle (involution): XOR low nibble with bits 4-7.
// Only touches bits 0-3, so it never crosses a 256-amp warp region.
__device__ __forceinline__ int SWZ(int i) { return i ^ ((i >> 4) & 15); }
// Insert a zero bit at position B.
__device__ __forceinline__ int insb(int x, int B) {
    return ((x >> B) << (B + 1)) | (x & ((1 << B) - 1));
}

// Layer-0 factored ring phase lookup (full 16-bit amp index, batch-free).
__device__ __forceinline__ float2 ring0_d0(int i) {
    return cmul(g_f0lo[i & 0x1FF], g_f0hi[((i >> 8) & 0xFF) | ((i & 1) << 8)]);
}
__device__ __forceinline__ float2 ring0_d1(int i) {
    return cmul(g_f1lo[i & 0x1FF], g_f1hi[((i >> 8) & 0xFF) | ((i & 1) << 8)]);
}

// ---------------------------------------------------------------------------
// Prep (tiny): factored ring tables, small ring tables, 60 composed unitaries.
// Ring term j couples amp bits (15-j) and (15-(j+1 mod 16)).
// ---------------------------------------------------------------------------
__global__ __launch_bounds__(512) void prep_kernel(
    const float* __restrict__ p0, const float* __restrict__ p1,
    const float* __restrict__ p2, const float* __restrict__ p3,
    float* __restrict__ out)
{
    int T = blockIdx.x * 512 + threadIdx.x;

    if (T < 512) {                      // lo tables (amp bits 8..0)
        float ph0 = 0.f, ph1 = 0.f;
        #pragma unroll
        for (int j = 7; j < 15; j++) {
            int x = ((T >> (15 - j)) ^ (T >> (14 - j))) & 1;
            float sg = x ? 0.5f : -0.5f;
            ph0 += sg * p0[4 * j + 3];
            ph1 += sg * p0[4 * j + 67];
        }
        g_f0lo[T] = make_float2(cosf(ph0), sinf(ph0));
        g_f1lo[T] = make_float2(cosf(ph1), sinf(ph1));
    } else if (T < 1024) {              // hi tables
        int ih = T - 512;
        float ph0 = 0.f, ph1 = 0.f;
        #pragma unroll
        for (int j = 0; j < 7; j++) {
            int x = ((ih >> (7 - j)) ^ (ih >> (6 - j))) & 1;
            float sg = x ? 0.5f : -0.5f;
            ph0 += sg * p0[4 * j + 3];
            ph1 += sg * p0[4 * j + 67];
        }
        {   // term j=15: amp bits 0 (ih bit 8) and 15 (ih bit 7)
            int x = ((ih >> 8) ^ (ih >> 7)) & 1;
            float sg = x ? 0.5f : -0.5f;
            ph0 += sg * p0[63];
            ph1 += sg * p0[127];
        }
        g_f0hi[ih] = make_float2(cosf(ph0), sinf(ph0));
        g_f1hi[ih] = make_float2(cosf(ph1), sinf(ph1));
    } else if (T < 1536) {              // layer1 ring (8 wires), 2 depths x 256
        int tt = T - 1024;
        int d = tt >> 8, idx = tt & 255;
        float ph = 0.f;
        #pragma unroll
        for (int j = 0; j < 8; j++) {
            int jn = (j + 1) & 7;
            int x = ((idx >> (7 - j)) ^ (idx >> (7 - jn))) & 1;
            ph += (x ? 0.5f : -0.5f) * p1[4 * j + 3 + 32 * d];
        }
        g_t1[tt] = make_float2(cosf(ph), sinf(ph));
    } else if (T < 1568) {              // layer2 ring (4 wires)
        int tt = T - 1536;
        int d = tt >> 4, idx = tt & 15;
        float ph = 0.f;
        #pragma unroll
        for (int j = 0; j < 4; j++) {
            int jn = (j + 1) & 3;
            int x = ((idx >> (3 - j)) ^ (idx >> (3 - jn))) & 1;
            ph += (x ? 0.5f : -0.5f) * p2[4 * j + 3 + 16 * d];
        }
        g_t2[tt] = make_float2(cosf(ph), sinf(ph));
    } else if (T < 1576) {              // layer3 (2 wires)
        int tt = T - 1568;
        int d = tt >> 2, idx = tt & 3;
        int x = ((idx >> 1) ^ idx) & 1;
        float sg = x ? 0.5f : -0.5f;
        float ph = sg * (p3[3 + 8 * d] + p3[7 + 8 * d]);
        g_t3[tt] = make_float2(cosf(ph), sinf(ph));
    } else if (T >= 1600 && T < 1660) { // compose 60 unitaries U = RX(c)*RZ(b)*RX(a)
        int t = T - 1600;
        const float* pp; int base;
        if (t < 32)      { pp = p0; int d = t >> 4;        int s = t & 15;       base = 4 * s + 64 * d; }
        else if (t < 48) { pp = p1; int d = (t - 32) >> 3; int s = (t - 32) & 7; base = 4 * s + 32 * d; }
        else if (t < 56) { pp = p2; int d = (t - 48) >> 2; int s = (t - 48) & 3; base = 4 * s + 16 * d; }
        else             { pp = p3; int d = (t - 56) >> 1; int s = (t - 56) & 1; base = 4 * s + 8 * d; }
        float a = pp[base] * 0.5f, b = pp[base + 1] * 0.5f, c = pp[base + 2] * 0.5f;
        float ca = cosf(a), sa = sinf(a);
        float cb = cosf(b), sb = sinf(b);
        float cc = cosf(c), sc = sinf(c);
        float2 RXa[4] = { {ca,0.f}, {0.f,-sa}, {0.f,-sa}, {ca,0.f} };
        float2 RZb[4] = { {cb,-sb}, {0.f,0.f}, {0.f,0.f}, {cb,sb} };
        float2 RXc[4] = { {cc,0.f}, {0.f,-sc}, {0.f,-sc}, {cc,0.f} };
        float2 M[4], U[4];
        mm2(RZb, RXa, M);
        mm2(RXc, M, U);
        g_U[t * 4 + 0] = U[0]; g_U[t * 4 + 1] = U[1];
        g_U[t * 4 + 2] = U[2]; g_U[t * 4 + 3] = U[3];
    } else if (T >= 1664 && T < 1680) {
        out[T - 1664] = 0.f;
    }
}

// ---------------------------------------------------------------------------
// 2-gate cell sweep: gate uh on local bit BH, ul on BL (BH > BL).
// Two cells (8 amps) per thread; ALL 8 loads issued before any math (MLP=8).
// WL=true: warp-local variant — requires BH,BL < 8; each thread's cells lie
// inside its own warp's 256-amp region, so only __syncwarp() is needed after.
// Caller appends the appropriate barrier.
// ---------------------------------------------------------------------------
template<int BH, int BL, bool WL, class LDF, class STF>
__device__ __forceinline__ void sweep2(int uh, int ul, LDF ld, STF st) {
    const float2 H0 = g_U[4*uh], H1 = g_U[4*uh+1], H2 = g_U[4*uh+2], H3 = g_U[4*uh+3];
    const float2 L0 = g_U[4*ul], L1 = g_U[4*ul+1], L2 = g_U[4*ul+2], L3 = g_U[4*ul+3];
    int b0, b1;
    if (WL) {
        int w = (int)threadIdx.x >> 5, l = (int)threadIdx.x & 31;
        b0 = (w << 8) | insb(insb(l, BL), BH);
        b1 = (w << 8) | insb(insb(l + 32, BL), BH);
    } else {
        b0 = insb(insb((int)threadIdx.x, BL), BH);
        b1 = insb(insb((int)threadIdx.x + NTP, BL), BH);
    }
    int j0 = b0 | (1 << BL), k0 = b0 | (1 << BH), m0 = k0 | (1 << BL);
    int j1 = b1 | (1 << BL), k1 = b1 | (1 << BH), m1 = k1 | (1 << BL);
    float2 a0 = ld(b0), a1 = ld(j0), a2 = ld(k0), a3 = ld(m0);
    float2 c0 = ld(b1), c1 = ld(j1), c2 = ld(k1), c3 = ld(m1);
    // cell 0
    float2 p00 = cadd(cmul(L0, a0), cmul(L1, a1));
    float2 p01 = cadd(cmul(L2, a0), cmul(L3, a1));
    float2 p10 = cadd(cmul(L0, a2), cmul(L1, a3));
    float2 p11 = cadd(cmul(L2, a2), cmul(L3, a3));
    st(b0, cadd(cmul(H0, p00), cmul(H1, p10)));
    st(j0, cadd(cmul(H0, p01), cmul(H1, p11)));
    st(k0, cadd(cmul(H2, p00), cmul(H3, p10)));
    st(m0, cadd(cmul(H2, p01), cmul(H3, p11)));
    // cell 1
    float2 q00 = cadd(cmul(L0, c0), cmul(L1, c1));
    float2 q01 = cadd(cmul(L2, c0), cmul(L3, c1));
    float2 q10 = cadd(cmul(L0, c2), cmul(L1, c3));
    float2 q11 = cadd(cmul(L2, c2), cmul(L3, c3));
    st(b1, cadd(cmul(H0, q00), cmul(H1, q10)));
    st(j1, cadd(cmul(H0, q01), cmul(H1, q11)));
    st(k1, cadd(cmul(H2, q00), cmul(H3, q10)));
    st(m1, cadd(cmul(H2, q01), cmul(H3, q11)));
}

// ---------------------------------------------------------------------------
// Fused diagonal + CNOT-layer permutation (XOR involution). new[l]=old[p]*ph(p).
// ---------------------------------------------------------------------------
template<class FXF, class PHF>
__device__ __forceinline__ void perm_ph(float2* s, FXF fx, PHF ph) {
    #pragma unroll
    for (int i = 0; i < 8; i++) {
        int l = threadIdx.x + i * NTP;
        int f = fx(l);
        int p = l ^ f;
        if (f == 0) {
            s[SWZ(l)] = cmul(s[SWZ(l)], ph(l));
        } else if (l < p) {
            float2 a = s[SWZ(l)], b = s[SWZ(p)];
            s[SWZ(l)] = cmul(b, ph(p));
            s[SWZ(p)] = cmul(a, ph(l));
        }
    }
    __syncthreads();
}

// ---------------------------------------------------------------------------
// Pass 1: local = amp bits 0..11 (wires 4..15). Layer0 d0 on wires 4..15.
// Local bit b holds wire 15-b -> U(15-b). Warp-local pairs on bits 0..7.
// ---------------------------------------------------------------------------
__global__ __launch_bounds__(NTP, 2) void pass1_kernel(
    const float* __restrict__ xre, const float* __restrict__ xim)
{
    __shared__ float2 s[4096];
    int b = blockIdx.x >> 4, tile = blockIdx.x & 15;
    int base = (b << 16) | (tile << 12);
    auto SLD = [&](int l) { return s[SWZ(l)]; };
    auto SST = [&](int l, float2 v) { s[SWZ(l)] = v; };
    sweep2<7, 0, true>(8, 15,
        [&](int l) { return make_float2(xre[base + l], xim[base + l]); }, SST);
    __syncwarp();
    sweep2<6, 1, true>(9, 14, SLD, SST);  __syncwarp();
    sweep2<5, 2, true>(10, 13, SLD, SST); __syncwarp();
    sweep2<4, 3, true>(11, 12, SLD, SST); __syncthreads();
    sweep2<11, 8, false>(4, 7, SLD, SST); __syncthreads();
    sweep2<10, 9, false>(5, 6, SLD,
        [&](int l, float2 v) { g_psi[base + l] = v; });
}

// ---------------------------------------------------------------------------
// Pass 2: local amp bits {0-4,7,9,11,12-15}. d0 on wires 0-3; ring D0; d1 on
// 12 local wires. Global amp bits {5,6,8,10}.
// d1 U-map: l11..l8 -> U16..19, l7->U20, l6->U22, l5->U24, l4->U27,
//           l3..l0 -> U28..31.
// ---------------------------------------------------------------------------
__device__ __forceinline__ int expand2x(int l) {
    return (l & 0x1F) | ((l & 0x20) << 2) | ((l & 0x40) << 3) | ((l & 0xF80) << 4);
}
__global__ __launch_bounds__(NTP, 2) void pass2_kernel() {
    __shared__ float2 s[4096];
    int b = blockIdx.x >> 4, tile = blockIdx.x & 15;
    unsigned tor = ((tile & 3) << 5) | ((tile & 4) << 6) | ((tile & 8) << 7);
    unsigned gb = (unsigned)b << 16;
    auto SLD = [&](int l) { return s[SWZ(l)]; };
    auto SST = [&](int l, float2 v) { s[SWZ(l)] = v; };
    // layer0 d0 on wires 0..3 (locals 11,10,9,8) — first sweep fused with load
    sweep2<11, 8, false>(0, 3,
        [&](int l) { return g_psi[gb | tor | expand2x(l)]; }, SST);
    __syncthreads();
    sweep2<10, 9, false>(1, 2, SLD, SST); __syncthreads();
    // layer0 d1; ring diag D0 folded into the first d1 sweep's load
    sweep2<7, 0, true>(20, 31,
        [&](int l) { return cmul(s[SWZ(l)], ring0_d0(tor | expand2x(l))); }, SST);
    __syncwarp();
    sweep2<6, 1, true>(22, 30, SLD, SST); __syncwarp();
    sweep2<5, 2, true>(24, 29, SLD, SST); __syncwarp();
    sweep2<4, 3, true>(27, 28, SLD, SST); __syncthreads();
    sweep2<11, 8, false>(16, 19, SLD, SST); __syncthreads();
    sweep2<10, 9, false>(17, 18, SLD,
        [&](int l, float2 v) { g_psi[gb | tor | expand2x(l)] = v; });
}

// ---------------------------------------------------------------------------
// Pass 3: local amp bits {0-6,8,10,12,14,15}. Global amp bits {7,9,11,13}.
// Local map: l11=w0 l10=w1 l9=w3 l8=w5 l7=w7 l6=w9 l5=w10 l4..l0=w11..w15.
// ---------------------------------------------------------------------------
__device__ __forceinline__ int expand3x(int l) {
    return (l & 0x7F) | ((l & 0x80) << 1) | ((l & 0x100) << 2) |
           ((l & 0x200) << 3) | ((l & 0xC00) << 4);
}
__global__ __launch_bounds__(NTP, 2) void pass3_kernel() {
    __shared__ float2 s[4096];
    int b = blockIdx.x >> 4, tile = blockIdx.x & 15;
    unsigned tor = ((tile & 1) << 7) | ((tile & 2) << 8) | ((tile & 4) << 9) | ((tile & 8) << 10);
    unsigned gb = (unsigned)b << 16;
    auto SLD = [&](int l) { return s[SWZ(l)]; };
    auto SST = [&](int l, float2 v) { s[SWZ(l)] = v; };
    // layer0 d1 leftovers: w5->l8(U21), w7->l7(U23), w9->l6(U25), w10->l5(U26)
    sweep2<8, 5, false>(21, 26,
        [&](int l) { return g_psi[gb | tor | expand3x(l)]; }, SST);
    __syncthreads();
    sweep2<7, 6, true>(23, 25, SLD, SST); __syncthreads();
    // ring D1 + all 8 pool CNOTs fused (targets l10,l9,l8,l7,l6,l4,l2,l0).
    {
        int fc = (((tile >> 3) & 1) << 9) | (((tile >> 2) & 1) << 8) |
                 (((tile >> 1) & 1) << 7) | ((tile & 1) << 6);
        perm_ph(s,
            [&](int l) {
                return ((((l >> 11) & 1) << 10) | (((l >> 5) & 1) << 4) |
                        (((l >> 3) & 1) << 2) | ((l >> 1) & 1)) | fc;
            },
            [&](int l) { return ring0_d1(tor | expand3x(l)); });
    }
    // layer1 d0 on wires 0,10,12,14 -> locals 11(U32),5(U37),3(U38),1(U39)
    sweep2<11, 1, false>(32, 39, SLD, SST); __syncthreads();
    sweep2<5, 3, true>(37, 38, SLD,
        [&](int l, float2 v) { g_psi[gb | tor | expand3x(l)] = v; });
}

// ---------------------------------------------------------------------------
// Pass 4: local amp bits {0-7,9,11,13,15}. Global amp bits {8,10,12,14}.
// Local map: l11=w0 l10=w2 l9=w4 l8=w6 l7=w8 l5=w10 l3=w12 l1=w14.
// Final diagonal (t3 d1) and final pool CNOT (ctrl=bit11, tgt=bit7) cannot
// change <Z(bit11)> — dropped. Measurement fused into the last unitary sweep.
// ---------------------------------------------------------------------------
__device__ __forceinline__ int expand4x(int l) {
    return (l & 0xFF) | ((l & 0x100) << 1) | ((l & 0x200) << 2) |
           ((l & 0x400) << 3) | ((l & 0x800) << 4);
}
__device__ __forceinline__ int p4_idx8(int l) {
    return ((l >> 4) & 0xF8) | ((l >> 3) & 4) | ((l >> 2) & 2) | ((l >> 1) & 1);
}
__device__ __forceinline__ int p4_idx4(int l) {
    return ((l >> 8) & 8) | ((l >> 7) & 4) | ((l >> 6) & 2) | ((l >> 3) & 1);
}
__device__ __forceinline__ int p4_idx2(int l) {
    return ((l >> 10) & 2) | ((l >> 7) & 1);
}
__global__ __launch_bounds__(NTP, 2) void pass4_kernel(float* __restrict__ out) {
    __shared__ float2 s[4096];
    __shared__ float ws[16];
    int tid = threadIdx.x;
    int b = blockIdx.x >> 4, tile = blockIdx.x & 15;
    unsigned tor = ((tile & 1) << 8) | ((tile & 2) << 9) | ((tile & 4) << 10) | ((tile & 8) << 11);
    unsigned gb = (unsigned)b << 16;
    auto SLD = [&](int l) { return s[SWZ(l)]; };
    auto SST = [&](int l, float2 v) { s[SWZ(l)] = v; };

    // layer1 d0 leftovers: w2->l10(U33), w4->l9(U34), w6->l8(U35), w8->l7(U36)
    sweep2<10, 9, false>(33, 34,
        [&](int l) { return g_psi[gb | tor | expand4x(l)]; }, SST);
    __syncthreads();
    sweep2<8, 7, false>(35, 36, SLD, SST); __syncthreads();
    // layer1 d1 (8 gates) with ring d0 folded into the first sweep
    sweep2<11, 8, false>(40, 43,
        [&](int l) { return cmul(s[SWZ(l)], g_t1[p4_idx8(l)]); }, SST);
    __syncthreads();
    sweep2<10, 9, false>(41, 42, SLD, SST); __syncthreads();
    sweep2<7, 5, true>(44, 45, SLD, SST);  __syncwarp();
    sweep2<3, 1, true>(46, 47, SLD, SST);  __syncthreads();
    // ring d1 + layer1 pool (l10<-l11, l8<-l9, l5<-l7, l1<-l3)
    perm_ph(s,
        [&](int l) {
            return (((l >> 11) & 1) << 10) | (((l >> 9) & 1) << 8) |
                   (((l >> 7) & 1) << 5) | (((l >> 3) & 1) << 1);
        },
        [&](int l) { return g_t1[256 + p4_idx8(l)]; });

    // layer2 d0: w0->l11(U48), w4->l9(U49), w8->l7(U50), w12->l3(U51)
    sweep2<11, 9, false>(48, 49, SLD, SST); __syncthreads();
    sweep2<7, 3, true>(50, 51, SLD, SST);   __syncthreads();
    // layer2 d1 with ring d0 folded
    sweep2<11, 9, false>(52, 53,
        [&](int l) { return cmul(s[SWZ(l)], g_t2[p4_idx4(l)]); }, SST);
    __syncthreads();
    sweep2<7, 3, true>(54, 55, SLD, SST); __syncthreads();
    // ring d1 + layer2 pool (l9<-l11, l3<-l7)
    perm_ph(s,
        [&](int l) {
            return (((l >> 11) & 1) << 9) | (((l >> 7) & 1) << 3);
        },
        [&](int l) { return g_t2[16 + p4_idx4(l)]; });

    // layer3 d0: w0->l11(U56), w8->l7(U57)
    sweep2<11, 7, false>(56, 57, SLD, SST); __syncthreads();
    // layer3 d1 sweep (U58 on l11, U59 on l7) with t3-d0 phase folded,
    // fused with Z-measurement on l11. t3-d1 + pool3 provably no-op for <Z>.
    float acc = 0.f;
    sweep2<11, 7, false>(58, 59,
        [&](int l) { return cmul(s[SWZ(l)], g_t3[p4_idx2(l)]); },
        [&](int l, float2 v) {
            float p = fmaf(v.x, v.x, v.y * v.y);
            acc += ((l >> 11) & 1) ? -p : p;
        });

    #pragma unroll
    for (int o = 16; o > 0; o >>= 1) acc += __shfl_xor_sync(0xFFFFFFFFu, acc, o);
    if ((tid & 31) == 0) ws[tid >> 5] = acc;
    __syncthreads();
    if (tid == 0) {
        float t = 0.f;
        #pragma unroll
        for (int k = 0; k < 16; k++) t += ws[k];
        atomicAdd(&out[b], t);
    }
}

// ---------------------------------------------------------------------------
extern "C" void kernel_launch(void* const* d_in, const int* in_sizes, int n_in,
                              void* d_out, int out_size) {
    const float* xre = (const float*)d_in[0];
    const float* xim = (const float*)d_in[1];
    const float* p0  = (const float*)d_in[2];
    const float* p1  = (const float*)d_in[3];
    const float* p2  = (const float*)d_in[4];
    const float* p3  = (const float*)d_in[5];
    float* out = (float*)d_out;

    prep_kernel<<<8, 512>>>(p0, p1, p2, p3, out);
    pass1_kernel<<<256, NTP>>>(xre, xim);
    pass2_kernel<<<256, NTP>>>();
    pass3_kernel<<<256, NTP>>>();
    pass4_kernel<<<256, NTP>>>(out);
}